// round 4
// baseline (speedup 1.0000x reference)
#include <cuda_runtime.h>
#include <cstdint>

#define BATCH 1024
#define SEQT  256
#define DIN   128
#define HID   512
#define ZD    64
#define G4    2048   // 4*HID
#define KTOT  640    // DIN + HID

__device__ float g_h[2][BATCH * HID];   // ping-pong hidden state (fp32)
__device__ float g_c[BATCH * HID];      // cell state

__device__ __forceinline__ float sigmoidf_(float v) {
    return 1.0f / (1.0f + __expf(-v));
}
__device__ __forceinline__ float softplusf_(float v) {
    return (v > 20.0f) ? v : log1pf(__expf(v));
}
__device__ __forceinline__ uint32_t f2tf32(float f) {
    uint32_t r;
    asm("cvt.rna.tf32.f32 %0, %1;" : "=r"(r) : "f"(f));
    return r;
}
__device__ __forceinline__ void mma_tf32(float c[4], const uint32_t a[4], uint32_t b0, uint32_t b1) {
    asm volatile(
        "mma.sync.aligned.m16n8k8.row.col.f32.tf32.tf32.f32 "
        "{%0,%1,%2,%3}, {%4,%5,%6,%7}, {%8,%9}, {%0,%1,%2,%3};"
        : "+f"(c[0]), "+f"(c[1]), "+f"(c[2]), "+f"(c[3])
        : "r"(a[0]), "r"(a[1]), "r"(a[2]), "r"(a[3]), "r"(b0), "r"(b1));
}

// Tiling: block = 64(M) x 128(N: 32 hidden x 4 gates), KT=16, 40 stages
constexpr int BM  = 64;
constexpr int BHU = 32;
constexpr int KT  = 16;
constexpr int NST = KTOT / KT;   // 40

// grid: (HID/BHU = 16, BATCH/BM = 16), block: 256 threads (8 warps: 2 M x 4 N-groups)
__global__ __launch_bounds__(256) void lstm_step_kernel(
    const float* __restrict__ x,
    const float* __restrict__ W,
    const float* __restrict__ U,
    const float* __restrict__ bias,
    int t)
{
    // Fragment-staged tiles.
    // sA[buf][kk8][tile_m][slot][word]: 16B slot per lane; word = x + 2*y
    //   (value at row = tile_m*16 + qid + 8x, k = kk8*8 + qtr + 4y; lane = qid*4+qtr; slot = lane^kk8)
    // sB[buf][kk8][wn][gp][slot][word]: word = (g&1)*2 + y, gp = g>>1
    //   (value at n-col: gate g, hidden j = wn*8 + qid, k = kk8*8 + qtr + 4y)
    __shared__ __align__(16) uint32_t sA[2][2][4][32][4];
    __shared__ __align__(16) uint32_t sB[2][2][4][2][32][4];

    const float* __restrict__ hin  = g_h[t & 1];
    float* __restrict__       hout = g_h[(t + 1) & 1];

    const int hh0 = blockIdx.x * BHU;
    const int bm0 = blockIdx.y * BM;
    const int tid = threadIdx.x;
    const int warp = tid >> 5;
    const int lane = tid & 31;
    const int wm = warp & 1;      // M half (32 rows)
    const int wn = warp >> 1;     // N group (8 hidden units x 4 gates)
    const int qid = lane >> 2;
    const int qtr = lane & 3;

    // ---- writer mappings
    // A: thread -> (row r 0..63, kq 0..3), loads float4 along k
    const int a_r   = tid >> 2;
    const int a_kq  = tid & 3;
    const int a_tile = a_r >> 4;
    const int a_qid  = a_r & 7;
    const int a_x    = (a_r >> 3) & 1;
    const int a_kk8  = a_kq >> 1;
    const int a_y    = a_kq & 1;
    // B: two parts; idx -> (k 0..15, gate g, jj0), loads float4 along hidden
    int b_k[2], b_g[2], b_jj0[2];
#pragma unroll
    for (int p = 0; p < 2; p++) {
        int idx = p * 256 + tid;
        b_k[p]  = idx & 15;
        int rest = idx >> 4;
        b_g[p]  = rest >> 3;
        b_jj0[p] = (rest & 7) * 4;
    }

    float acc[2][4][4];
#pragma unroll
    for (int mt = 0; mt < 2; mt++)
#pragma unroll
        for (int g = 0; g < 4; g++)
#pragma unroll
            for (int q = 0; q < 4; q++)
                acc[mt][g][q] = 0.0f;

    // ---- STS helpers (inline lambdas via macros would hurt readability; write plainly)
    auto store_A = [&](int buf, float4 v) {
#pragma unroll
        for (int e = 0; e < 4; e++) {
            float vv = (e == 0) ? v.x : (e == 1) ? v.y : (e == 2) ? v.z : v.w;
            int lane_w = a_qid * 4 + e;
            sA[buf][a_kk8][a_tile][lane_w ^ a_kk8][a_x + 2 * a_y] = f2tf32(vv);
        }
    };
    auto store_B = [&](int buf, int p, float4 v) {
        int kk8 = b_k[p] >> 3;
        int y   = (b_k[p] >> 2) & 1;
        int qb  = b_k[p] & 3;
        int word = (b_g[p] & 1) * 2 + y;
        int gp   = b_g[p] >> 1;
#pragma unroll
        for (int e = 0; e < 4; e++) {
            float vv = (e == 0) ? v.x : (e == 1) ? v.y : (e == 2) ? v.z : v.w;
            int j = b_jj0[p] + e;
            int lane_w = (j & 7) * 4 + qb;
            sB[buf][kk8][j >> 3][gp][lane_w ^ kk8][word] = f2tf32(vv);
        }
    };

    // ---- prologue: stage 0 into buf 0
    {
        const float* asrc = x + (size_t)(bm0 + a_r) * (SEQT * DIN) + (size_t)t * DIN + a_kq * 4;
        store_A(0, *reinterpret_cast<const float4*>(asrc));
#pragma unroll
        for (int p = 0; p < 2; p++) {
            const float* bsrc = W + (size_t)b_k[p] * G4 + b_g[p] * HID + hh0 + b_jj0[p];
            store_B(0, p, *reinterpret_cast<const float4*>(bsrc));
        }
    }
    __syncthreads();

    int cur = 0;
    for (int s = 0; s < NST; s++) {
        // prefetch stage s+1 into registers
        float4 av;
        float4 bv[2];
        const bool has_next = (s + 1 < NST);
        if (has_next) {
            const int kb = (s + 1) * KT;
            const float* asrc = (kb < DIN)
                ? x   + (size_t)(bm0 + a_r) * (SEQT * DIN) + (size_t)t * DIN + kb + a_kq * 4
                : hin + (size_t)(bm0 + a_r) * HID + (kb - DIN) + a_kq * 4;
            av = *reinterpret_cast<const float4*>(asrc);
#pragma unroll
            for (int p = 0; p < 2; p++) {
                int kg = kb + b_k[p];
                const float* bsrc = (kg < DIN)
                    ? W + (size_t)kg * G4 + b_g[p] * HID + hh0 + b_jj0[p]
                    : U + (size_t)(kg - DIN) * G4 + b_g[p] * HID + hh0 + b_jj0[p];
                bv[p] = *reinterpret_cast<const float4*>(bsrc);
            }
        }

        // compute on buf[cur]: 2 x (4 LDS.128 + 8 MMA)
#pragma unroll
        for (int kk8 = 0; kk8 < 2; kk8++) {
            const int slot = lane ^ kk8;
            uint32_t af[2][4];
#pragma unroll
            for (int mt = 0; mt < 2; mt++) {
                const uint4 va = *reinterpret_cast<const uint4*>(&sA[cur][kk8][wm * 2 + mt][slot][0]);
                af[mt][0] = va.x; af[mt][1] = va.y; af[mt][2] = va.z; af[mt][3] = va.w;
            }
            uint4 vb0 = *reinterpret_cast<const uint4*>(&sB[cur][kk8][wn][0][slot][0]);
            uint4 vb1 = *reinterpret_cast<const uint4*>(&sB[cur][kk8][wn][1][slot][0]);
#pragma unroll
            for (int mt = 0; mt < 2; mt++) {
                mma_tf32(acc[mt][0], af[mt], vb0.x, vb0.y);
                mma_tf32(acc[mt][1], af[mt], vb0.z, vb0.w);
                mma_tf32(acc[mt][2], af[mt], vb1.x, vb1.y);
                mma_tf32(acc[mt][3], af[mt], vb1.z, vb1.w);
            }
        }

        if (has_next) {
            const int nb = cur ^ 1;
            store_A(nb, av);
            store_B(nb, 0, bv[0]);
            store_B(nb, 1, bv[1]);
        }
        __syncthreads();
        cur ^= 1;
    }

    // ---- LSTM pointwise epilogue (register-local gates, same mapping as R2)
#pragma unroll
    for (int mt = 0; mt < 2; mt++) {
#pragma unroll
        for (int half = 0; half < 2; half++) {
            int row = bm0 + wm * 32 + mt * 16 + qid + half * 8;
#pragma unroll
            for (int u = 0; u < 2; u++) {
                int hh = hh0 + wn * 8 + qtr * 2 + u;
                int q  = half * 2 + u;
                float gi = acc[mt][0][q] + bias[hh];
                float gf = acc[mt][1][q] + bias[HID + hh];
                float gg = acc[mt][2][q] + bias[2 * HID + hh];
                float go = acc[mt][3][q] + bias[3 * HID + hh];
                float iv = sigmoidf_(gi);
                float fv = sigmoidf_(gf);
                float gv = softplusf_(gg);
                float ov = sigmoidf_(go);
                size_t off = (size_t)row * HID + hh;
                float cn = fv * g_c[off] + iv * gv;
                g_c[off]  = cn;
                hout[off] = ov * softplusf_(cn);
            }
        }
    }
}

__global__ void zero_state_kernel() {
    int i = blockIdx.x * blockDim.x + threadIdx.x;
    if (i < BATCH * HID) {
        g_h[0][i] = 0.0f;
        g_c[i]    = 0.0f;
    }
}

// Final h is in g_h[0] (t=255 writes buf (255+1)&1 = 0). Head stays pure fp32.
__global__ void vae_head_kernel(
    const float* __restrict__ eps,
    const float* __restrict__ Wm, const float* __restrict__ bm,
    const float* __restrict__ Wv, const float* __restrict__ bv,
    float* __restrict__ out)
{
    int b = blockIdx.x;
    int z = threadIdx.x;
    const float* __restrict__ h = g_h[0] + (size_t)b * HID;
    float am = 0.0f, av = 0.0f;
#pragma unroll 8
    for (int k = 0; k < HID; k++) {
        float hv = h[k];
        am = fmaf(hv, Wm[(size_t)k * ZD + z], am);
        av = fmaf(hv, Wv[(size_t)k * ZD + z], av);
    }
    float mu = am + bm[z];
    float lv = av + bv[z];
    size_t o = (size_t)b * ZD + z;
    out[o]                          = mu;
    out[(size_t)BATCH * ZD + o]     = lv;
    out[2 * (size_t)BATCH * ZD + o] = mu + eps[o] * __expf(0.5f * lv);
}

extern "C" void kernel_launch(void* const* d_in, const int* in_sizes, int n_in,
                              void* d_out, int out_size)
{
    const float* x    = (const float*)d_in[0];
    const float* eps  = (const float*)d_in[1];
    const float* W    = (const float*)d_in[2];
    const float* U    = (const float*)d_in[3];
    const float* bias = (const float*)d_in[4];
    const float* Wm   = (const float*)d_in[5];
    const float* bm   = (const float*)d_in[6];
    const float* Wv   = (const float*)d_in[7];
    const float* bv   = (const float*)d_in[8];
    float* out = (float*)d_out;

    zero_state_kernel<<<(BATCH * HID + 255) / 256, 256>>>();

    dim3 grid(HID / BHU, BATCH / BM);   // (16, 16) = 256 blocks
    for (int t = 0; t < SEQT; t++) {
        lstm_step_kernel<<<grid, 256>>>(x, W, U, bias, t);
    }

    vae_head_kernel<<<BATCH, ZD>>>(eps, Wm, bm, Wv, bv, out);
}

// round 6
// speedup vs baseline: 1.3539x; 1.3539x over previous
#include <cuda_runtime.h>
#include <cstdint>

#define BATCH 1024
#define SEQT  256
#define DIN   128
#define HID   512
#define ZD    64
#define G4    2048   // 4*HID
#define KTOT  640    // DIN + HID

__device__ float g_h[2][BATCH * HID];   // ping-pong hidden state (stored tf32-rounded)
__device__ float g_c[BATCH * HID];      // cell state (full fp32)
__device__ float g_wt[DIN * G4];        // W pre-rounded to tf32
__device__ float g_ut[HID * G4];        // U pre-rounded to tf32

__device__ __forceinline__ float sigmoidf_(float v) {
    return 1.0f / (1.0f + __expf(-v));
}
__device__ __forceinline__ float softplusf_(float v) {
    return (v > 20.0f) ? v : log1pf(__expf(v));
}
__device__ __forceinline__ float f2tf32f(float f) {
    uint32_t r;
    asm("cvt.rna.tf32.f32 %0, %1;" : "=r"(r) : "f"(f));
    return __uint_as_float(r);
}
__device__ __forceinline__ void mma_tf32(float c[4], const float a[4], float b0, float b1) {
    asm volatile(
        "mma.sync.aligned.m16n8k8.row.col.f32.tf32.tf32.f32 "
        "{%0,%1,%2,%3}, {%4,%5,%6,%7}, {%8,%9}, {%0,%1,%2,%3};"
        : "+f"(c[0]), "+f"(c[1]), "+f"(c[2]), "+f"(c[3])
        : "r"(__float_as_uint(a[0])), "r"(__float_as_uint(a[1])),
          "r"(__float_as_uint(a[2])), "r"(__float_as_uint(a[3])),
          "r"(__float_as_uint(b0)), "r"(__float_as_uint(b1)));
}

// Tiling: block = 128(M) x 128(N local), KT=16, 40 stages
// Local B column layout (group-major, matching the fragment reader):
//   n = grp*32 + g*8 + j   (grp 0..3 = warp n-group, g = gate, j = hidden-in-8)
//   weight column = g*HID + hh0 + grp*8 + j
constexpr int BM  = 128;
constexpr int BHU = 32;
constexpr int KT  = 16;
constexpr int NST = KTOT / KT;   // 40
constexpr int LDA = BM + 8;      // 136
constexpr int LDB = 128 + 8;     // 136

// grid: (HID/BHU = 16, BATCH/BM = 8) = 128 CTAs; 256 threads (8 warps: 2 M x 4 N-groups)
__global__ __launch_bounds__(256, 1) void lstm_step_kernel(
    const float* __restrict__ x,
    const float* __restrict__ bias,
    int t)
{
    __shared__ float As[2][KT][LDA];
    __shared__ float Bs[2][KT][LDB];

    const float* __restrict__ hin  = g_h[t & 1];
    float* __restrict__       hout = g_h[(t + 1) & 1];

    const int hh0 = blockIdx.x * BHU;
    const int bm0 = blockIdx.y * BM;
    const int tid = threadIdx.x;
    const int warp = tid >> 5;
    const int lane = tid & 31;
    const int wm = warp & 1;      // M half (64 rows)
    const int wn = warp >> 1;     // N group (8 hidden units x 4 gates)
    const int qid = lane >> 2;
    const int qtr = lane & 3;

    // ---- writer mappings
    // A: 128 rows x 16 k = 512 float4 along k; 2 per thread.
    // B: 16 k x 128 n = 512 float4 along n; 2 per thread. GROUP-MAJOR mapping (bug fix):
    int b_k[2], b_n[2], b_col[2];
#pragma unroll
    for (int p = 0; p < 2; p++) {
        int idx = p * 256 + tid;
        int n4  = idx & 31;
        b_k[p]  = idx >> 5;
        b_n[p]  = n4 * 4;
        int j0  = b_n[p] & 7;          // 0 or 4
        int g   = (b_n[p] >> 3) & 3;   // gate
        int grp = b_n[p] >> 5;         // n-group
        b_col[p] = g * HID + hh0 + grp * 8 + j0;
    }

    float acc[4][4][4];   // [m_tile][gate][c0..c3]
#pragma unroll
    for (int mt = 0; mt < 4; mt++)
#pragma unroll
        for (int g = 0; g < 4; g++)
#pragma unroll
            for (int q = 0; q < 4; q++)
                acc[mt][g][q] = 0.0f;

    // ---- prologue: stage 0 (k 0..15, all from x/W)
    {
#pragma unroll
        for (int i = 0; i < 2; i++) {
            int idx = i * 256 + tid;
            int row = idx & 127, kq = idx >> 7;
            const float* src = x + (size_t)(bm0 + row) * (SEQT * DIN) + (size_t)t * DIN + kq * 4;
            float4 v = *reinterpret_cast<const float4*>(src);
            As[0][kq * 4 + 0][row] = f2tf32f(v.x);
            As[0][kq * 4 + 1][row] = f2tf32f(v.y);
            As[0][kq * 4 + 2][row] = f2tf32f(v.z);
            As[0][kq * 4 + 3][row] = f2tf32f(v.w);
        }
#pragma unroll
        for (int p = 0; p < 2; p++) {
            const float* src = g_wt + (size_t)b_k[p] * G4 + b_col[p];
            *reinterpret_cast<float4*>(&Bs[0][b_k[p]][b_n[p]]) =
                *reinterpret_cast<const float4*>(src);
        }
    }
    __syncthreads();

    int cur = 0;
    for (int s = 0; s < NST; s++) {
        // ---- prefetch stage s+1 into registers
        float4 av[2];
        float4 bv[2];
        const bool has_next = (s + 1 < NST);
        bool next_from_x = false;
        if (has_next) {
            const int kb = (s + 1) * KT;
            next_from_x = (kb < DIN);
#pragma unroll
            for (int i = 0; i < 2; i++) {
                int idx = i * 256 + tid;
                int row = idx & 127, kq = idx >> 7;
                const float* src = next_from_x
                    ? x   + (size_t)(bm0 + row) * (SEQT * DIN) + (size_t)t * DIN + kb + kq * 4
                    : hin + (size_t)(bm0 + row) * HID + (kb - DIN) + kq * 4;
                av[i] = *reinterpret_cast<const float4*>(src);
            }
#pragma unroll
            for (int p = 0; p < 2; p++) {
                int kg = kb + b_k[p];
                const float* src = (kg < DIN)
                    ? g_wt + (size_t)kg * G4 + b_col[p]
                    : g_ut + (size_t)(kg - DIN) * G4 + b_col[p];
                bv[p] = *reinterpret_cast<const float4*>(src);
            }
        }

        // ---- compute on buf[cur]: 2 x (24 LDS.32 + 16 MMA)
#pragma unroll
        for (int kk8 = 0; kk8 < 2; kk8++) {
            const int k0 = kk8 * 8;
            float af[4][4];
#pragma unroll
            for (int mt = 0; mt < 4; mt++) {
                int m = wm * 64 + mt * 16 + qid;
                af[mt][0] = As[cur][k0 + qtr][m];
                af[mt][1] = As[cur][k0 + qtr][m + 8];
                af[mt][2] = As[cur][k0 + 4 + qtr][m];
                af[mt][3] = As[cur][k0 + 4 + qtr][m + 8];
            }
            float bf[4][2];
#pragma unroll
            for (int g = 0; g < 4; g++) {
                int n = wn * 32 + g * 8 + qid;
                bf[g][0] = Bs[cur][k0 + qtr][n];
                bf[g][1] = Bs[cur][k0 + 4 + qtr][n];
            }
#pragma unroll
            for (int mt = 0; mt < 4; mt++)
#pragma unroll
                for (int g = 0; g < 4; g++)
                    mma_tf32(acc[mt][g], af[mt], bf[g][0], bf[g][1]);
        }

        // ---- store prefetched stage (h/W/U already tf32; x needs cvt)
        if (has_next) {
            const int nb = cur ^ 1;
#pragma unroll
            for (int i = 0; i < 2; i++) {
                int idx = i * 256 + tid;
                int row = idx & 127, kq = idx >> 7;
                if (next_from_x) {
                    As[nb][kq * 4 + 0][row] = f2tf32f(av[i].x);
                    As[nb][kq * 4 + 1][row] = f2tf32f(av[i].y);
                    As[nb][kq * 4 + 2][row] = f2tf32f(av[i].z);
                    As[nb][kq * 4 + 3][row] = f2tf32f(av[i].w);
                } else {
                    As[nb][kq * 4 + 0][row] = av[i].x;
                    As[nb][kq * 4 + 1][row] = av[i].y;
                    As[nb][kq * 4 + 2][row] = av[i].z;
                    As[nb][kq * 4 + 3][row] = av[i].w;
                }
            }
#pragma unroll
            for (int p = 0; p < 2; p++)
                *reinterpret_cast<float4*>(&Bs[nb][b_k[p]][b_n[p]]) = bv[p];
        }
        __syncthreads();
        cur ^= 1;
    }

    // ---- LSTM pointwise epilogue (register-local gates)
#pragma unroll
    for (int mt = 0; mt < 4; mt++) {
#pragma unroll
        for (int half = 0; half < 2; half++) {
            int row = bm0 + wm * 64 + mt * 16 + qid + half * 8;
#pragma unroll
            for (int u = 0; u < 2; u++) {
                int hh = hh0 + wn * 8 + qtr * 2 + u;
                int q  = half * 2 + u;
                float gi = acc[mt][0][q] + bias[hh];
                float gf = acc[mt][1][q] + bias[HID + hh];
                float gg = acc[mt][2][q] + bias[2 * HID + hh];
                float go = acc[mt][3][q] + bias[3 * HID + hh];
                float iv = sigmoidf_(gi);
                float fv = sigmoidf_(gf);
                float gv = softplusf_(gg);
                float ov = sigmoidf_(go);
                size_t off = (size_t)row * HID + hh;
                float cn = fv * g_c[off] + iv * gv;
                g_c[off]  = cn;
                hout[off] = f2tf32f(ov * softplusf_(cn));   // pre-rounded for next step's A
            }
        }
    }
}

// ---- pre-round W and U to tf32 once per launch (2.6 MB total)
__global__ void prep_weights_kernel(const float* __restrict__ W, const float* __restrict__ U) {
    int i = blockIdx.x * blockDim.x + threadIdx.x;
    int stride = gridDim.x * blockDim.x;
    for (int k = i; k < DIN * G4 / 4; k += stride) {
        float4 v = reinterpret_cast<const float4*>(W)[k];
        v.x = f2tf32f(v.x); v.y = f2tf32f(v.y); v.z = f2tf32f(v.z); v.w = f2tf32f(v.w);
        reinterpret_cast<float4*>(g_wt)[k] = v;
    }
    for (int k = i; k < HID * G4 / 4; k += stride) {
        float4 v = reinterpret_cast<const float4*>(U)[k];
        v.x = f2tf32f(v.x); v.y = f2tf32f(v.y); v.z = f2tf32f(v.z); v.w = f2tf32f(v.w);
        reinterpret_cast<float4*>(g_ut)[k] = v;
    }
}

__global__ void zero_state_kernel() {
    int i = blockIdx.x * blockDim.x + threadIdx.x;
    if (i < BATCH * HID) {
        g_h[0][i] = 0.0f;
        g_c[i]    = 0.0f;
    }
}

// Final h is in g_h[0] (t=255 writes buf (255+1)&1 = 0). Head stays fp32.
__global__ void vae_head_kernel(
    const float* __restrict__ eps,
    const float* __restrict__ Wm, const float* __restrict__ bm,
    const float* __restrict__ Wv, const float* __restrict__ bv,
    float* __restrict__ out)
{
    int b = blockIdx.x;
    int z = threadIdx.x;
    const float* __restrict__ h = g_h[0] + (size_t)b * HID;
    float am = 0.0f, av = 0.0f;
#pragma unroll 8
    for (int k = 0; k < HID; k++) {
        float hv = h[k];
        am = fmaf(hv, Wm[(size_t)k * ZD + z], am);
        av = fmaf(hv, Wv[(size_t)k * ZD + z], av);
    }
    float mu = am + bm[z];
    float lv = av + bv[z];
    size_t o = (size_t)b * ZD + z;
    out[o]                          = mu;
    out[(size_t)BATCH * ZD + o]     = lv;
    out[2 * (size_t)BATCH * ZD + o] = mu + eps[o] * __expf(0.5f * lv);
}

extern "C" void kernel_launch(void* const* d_in, const int* in_sizes, int n_in,
                              void* d_out, int out_size)
{
    const float* x    = (const float*)d_in[0];
    const float* eps  = (const float*)d_in[1];
    const float* W    = (const float*)d_in[2];
    const float* U    = (const float*)d_in[3];
    const float* bias = (const float*)d_in[4];
    const float* Wm   = (const float*)d_in[5];
    const float* bm   = (const float*)d_in[6];
    const float* Wv   = (const float*)d_in[7];
    const float* bv   = (const float*)d_in[8];
    float* out = (float*)d_out;

    prep_weights_kernel<<<256, 256>>>(W, U);
    zero_state_kernel<<<(BATCH * HID + 255) / 256, 256>>>();

    dim3 grid(HID / BHU, BATCH / BM);   // (16, 8) = 128 CTAs
    for (int t = 0; t < SEQT; t++) {
        lstm_step_kernel<<<grid, 256>>>(x, bias, t);
    }

    vae_head_kernel<<<BATCH, ZD>>>(eps, Wm, bm, Wv, bv, out);
}

// round 7
// speedup vs baseline: 1.9133x; 1.4132x over previous
#include <cuda_runtime.h>
#include <cstdint>

#define BATCH 1024
#define SEQT  256
#define DIN   128
#define HID   512
#define ZD    64
#define G4    2048   // 4*HID
#define KTOT  640    // DIN + HID

__device__ float g_h[2][BATCH * HID];   // ping-pong hidden state (tf32-rounded)
__device__ float g_c[BATCH * HID];      // cell state (full fp32)
__device__ float g_wt[DIN * G4];        // W pre-rounded to tf32
__device__ float g_ut[HID * G4];        // U pre-rounded to tf32

__device__ __forceinline__ float sigmoidf_(float v) {
    return 1.0f / (1.0f + __expf(-v));
}
__device__ __forceinline__ float softplusf_(float v) {
    return (v > 20.0f) ? v : log1pf(__expf(v));
}
__device__ __forceinline__ float f2tf32f(float f) {
    uint32_t r;
    asm("cvt.rna.tf32.f32 %0, %1;" : "=r"(r) : "f"(f));
    return __uint_as_float(r);
}
__device__ __forceinline__ void mma_tf32(float c[4], const float a[4], float b0, float b1) {
    asm volatile(
        "mma.sync.aligned.m16n8k8.row.col.f32.tf32.tf32.f32 "
        "{%0,%1,%2,%3}, {%4,%5,%6,%7}, {%8,%9}, {%0,%1,%2,%3};"
        : "+f"(c[0]), "+f"(c[1]), "+f"(c[2]), "+f"(c[3])
        : "r"(__float_as_uint(a[0])), "r"(__float_as_uint(a[1])),
          "r"(__float_as_uint(a[2])), "r"(__float_as_uint(a[3])),
          "r"(__float_as_uint(b0)), "r"(__float_as_uint(b1)));
}
__device__ __forceinline__ void cp16(void* dst, const void* src) {
    uint32_t d = (uint32_t)__cvta_generic_to_shared(dst);
    asm volatile("cp.async.cg.shared.global [%0], [%1], 16;" :: "r"(d), "l"(src));
}

// Tiling: CTA = 64(M) x 128(N local: group-major n = grp*32 + g*8 + j), KT=32, 20 stages
constexpr int BM  = 64;
constexpr int BHU = 32;
constexpr int KT  = 32;
constexpr int NST = KTOT / KT;   // 20
constexpr int LDA = 36;          // A [m][k] floats; bank = (4m + k) % 32, conflict-free
constexpr int LDB = 136;         // B [k][n] floats; bank = (8k + n) % 32, conflict-free
constexpr int A_STAGE = BM * LDA;       // 2304 floats
constexpr int B_STAGE = KT * LDB;       // 4352 floats
constexpr int SMEM_FLOATS = 3 * (A_STAGE + B_STAGE);
constexpr int SMEM_BYTES  = SMEM_FLOATS * 4;   // 79872

// issue cp.async for one stage into buffer `buf`
__device__ __forceinline__ void issue_stage(
    float* As, float* Bs, int buf, int kb, int t,
    const float* __restrict__ x, const float* __restrict__ hin,
    int bm0, int hh0, int tid)
{
    float* A = As + buf * A_STAGE;
    float* B = Bs + buf * B_STAGE;
    const bool from_x = (kb < DIN);
    // A tile: 64 rows x 32 k = 512 x 16B chunks; 2 per thread
#pragma unroll
    for (int i = 0; i < 2; i++) {
        int c = i * 256 + tid;
        int m = c >> 3, kc = c & 7;
        const float* src = from_x
            ? x   + (size_t)(bm0 + m) * (SEQT * DIN) + (size_t)t * DIN + kb + kc * 4
            : hin + (size_t)(bm0 + m) * HID + (kb - DIN) + kc * 4;
        cp16(A + m * LDA + kc * 4, src);
    }
    // B tile: 32 k x 128 n = 1024 x 16B chunks; 4 per thread
#pragma unroll
    for (int i = 0; i < 4; i++) {
        int c = i * 256 + tid;
        int k = c >> 5, nc = c & 31;
        int n = nc * 4;
        int j0  = n & 7;
        int g   = (n >> 3) & 3;
        int grp = n >> 5;
        int col = g * HID + hh0 + grp * 8 + j0;
        int kg  = kb + k;
        const float* src = (kg < DIN)
            ? g_wt + (size_t)kg * G4 + col
            : g_ut + (size_t)(kg - DIN) * G4 + col;
        cp16(B + k * LDB + n, src);
    }
    asm volatile("cp.async.commit_group;" ::: "memory");
}

// grid: (HID/BHU = 16, BATCH/BM = 16) = 256 CTAs; 256 threads (8 warps: 2 M x 4 N-groups)
__global__ __launch_bounds__(256, 2) void lstm_step_kernel(
    const float* __restrict__ x,
    const float* __restrict__ bias,
    int t)
{
    extern __shared__ float smem[];
    float* As = smem;
    float* Bs = smem + 3 * A_STAGE;

    const float* __restrict__ hin  = g_h[t & 1];
    float* __restrict__       hout = g_h[(t + 1) & 1];

    const int hh0 = blockIdx.x * BHU;
    const int bm0 = blockIdx.y * BM;
    const int tid = threadIdx.x;
    const int warp = tid >> 5;
    const int lane = tid & 31;
    const int wm = warp & 1;      // M half (32 rows)
    const int wn = warp >> 1;     // N group (8 hidden x 4 gates)
    const int qid = lane >> 2;
    const int qtr = lane & 3;

    float acc[2][4][4];
#pragma unroll
    for (int mt = 0; mt < 2; mt++)
#pragma unroll
        for (int g = 0; g < 4; g++)
#pragma unroll
            for (int q = 0; q < 4; q++)
                acc[mt][g][q] = 0.0f;

    // prologue: stages 0 and 1 in flight
    issue_stage(As, Bs, 0, 0,  t, x, hin, bm0, hh0, tid);
    issue_stage(As, Bs, 1, KT, t, x, hin, bm0, hh0, tid);

    int buf = 0;
    for (int s = 0; s < NST; s++) {
        asm volatile("cp.async.wait_group 1;" ::: "memory");  // stage s complete
        __syncthreads();

        // issue stage s+2 into the buffer freed by compute(s-1)
        if (s + 2 < NST) {
            int nb = (buf + 2) % 3;
            issue_stage(As, Bs, nb, (s + 2) * KT, t, x, hin, bm0, hh0, tid);
        } else {
            asm volatile("cp.async.commit_group;" ::: "memory");  // keep group count flowing
        }

        // compute stage s
        const float* A = As + buf * A_STAGE;
        const float* B = Bs + buf * B_STAGE;
#pragma unroll
        for (int kk8 = 0; kk8 < 4; kk8++) {
            const int k0 = kk8 * 8;
            float af[2][4];
#pragma unroll
            for (int mt = 0; mt < 2; mt++) {
                int m = wm * 32 + mt * 16 + qid;
                af[mt][0] = A[m * LDA + k0 + qtr];
                af[mt][1] = A[(m + 8) * LDA + k0 + qtr];
                af[mt][2] = A[m * LDA + k0 + 4 + qtr];
                af[mt][3] = A[(m + 8) * LDA + k0 + 4 + qtr];
            }
            float bf[4][2];
#pragma unroll
            for (int g = 0; g < 4; g++) {
                int n = wn * 32 + g * 8 + qid;
                bf[g][0] = B[(k0 + qtr) * LDB + n];
                bf[g][1] = B[(k0 + 4 + qtr) * LDB + n];
            }
#pragma unroll
            for (int mt = 0; mt < 2; mt++)
#pragma unroll
                for (int g = 0; g < 4; g++)
                    mma_tf32(acc[mt][g], af[mt], bf[g][0], bf[g][1]);
        }
        buf = (buf + 1) % 3;
    }

    // ---- LSTM pointwise epilogue (register-local gates; mapping proven in R2)
#pragma unroll
    for (int mt = 0; mt < 2; mt++) {
#pragma unroll
        for (int half = 0; half < 2; half++) {
            int row = bm0 + wm * 32 + mt * 16 + qid + half * 8;
#pragma unroll
            for (int u = 0; u < 2; u++) {
                int hh = hh0 + wn * 8 + qtr * 2 + u;
                int q  = half * 2 + u;
                float gi = acc[mt][0][q] + bias[hh];
                float gf = acc[mt][1][q] + bias[HID + hh];
                float gg = acc[mt][2][q] + bias[2 * HID + hh];
                float go = acc[mt][3][q] + bias[3 * HID + hh];
                float iv = sigmoidf_(gi);
                float fv = sigmoidf_(gf);
                float gv = softplusf_(gg);
                float ov = sigmoidf_(go);
                size_t off = (size_t)row * HID + hh;
                float cn = fv * g_c[off] + iv * gv;
                g_c[off]  = cn;
                hout[off] = f2tf32f(ov * softplusf_(cn));   // pre-rounded for next step
            }
        }
    }
}

// ---- pre-round W and U to tf32 once per launch
__global__ void prep_weights_kernel(const float* __restrict__ W, const float* __restrict__ U) {
    int i = blockIdx.x * blockDim.x + threadIdx.x;
    int stride = gridDim.x * blockDim.x;
    for (int k = i; k < DIN * G4 / 4; k += stride) {
        float4 v = reinterpret_cast<const float4*>(W)[k];
        v.x = f2tf32f(v.x); v.y = f2tf32f(v.y); v.z = f2tf32f(v.z); v.w = f2tf32f(v.w);
        reinterpret_cast<float4*>(g_wt)[k] = v;
    }
    for (int k = i; k < HID * G4 / 4; k += stride) {
        float4 v = reinterpret_cast<const float4*>(U)[k];
        v.x = f2tf32f(v.x); v.y = f2tf32f(v.y); v.z = f2tf32f(v.z); v.w = f2tf32f(v.w);
        reinterpret_cast<float4*>(g_ut)[k] = v;
    }
}

__global__ void zero_state_kernel() {
    int i = blockIdx.x * blockDim.x + threadIdx.x;
    if (i < BATCH * HID) {
        g_h[0][i] = 0.0f;
        g_c[i]    = 0.0f;
    }
}

// Final h is in g_h[0] (t=255 writes buf (255+1)&1 = 0). Head stays fp32.
__global__ void vae_head_kernel(
    const float* __restrict__ eps,
    const float* __restrict__ Wm, const float* __restrict__ bm,
    const float* __restrict__ Wv, const float* __restrict__ bv,
    float* __restrict__ out)
{
    int b = blockIdx.x;
    int z = threadIdx.x;
    const float* __restrict__ h = g_h[0] + (size_t)b * HID;
    float am = 0.0f, av = 0.0f;
#pragma unroll 8
    for (int k = 0; k < HID; k++) {
        float hv = h[k];
        am = fmaf(hv, Wm[(size_t)k * ZD + z], am);
        av = fmaf(hv, Wv[(size_t)k * ZD + z], av);
    }
    float mu = am + bm[z];
    float lv = av + bv[z];
    size_t o = (size_t)b * ZD + z;
    out[o]                          = mu;
    out[(size_t)BATCH * ZD + o]     = lv;
    out[2 * (size_t)BATCH * ZD + o] = mu + eps[o] * __expf(0.5f * lv);
}

extern "C" void kernel_launch(void* const* d_in, const int* in_sizes, int n_in,
                              void* d_out, int out_size)
{
    const float* x    = (const float*)d_in[0];
    const float* eps  = (const float*)d_in[1];
    const float* W    = (const float*)d_in[2];
    const float* U    = (const float*)d_in[3];
    const float* bias = (const float*)d_in[4];
    const float* Wm   = (const float*)d_in[5];
    const float* bm   = (const float*)d_in[6];
    const float* Wv   = (const float*)d_in[7];
    const float* bv   = (const float*)d_in[8];
    float* out = (float*)d_out;

    cudaFuncSetAttribute(lstm_step_kernel,
                         cudaFuncAttributeMaxDynamicSharedMemorySize, SMEM_BYTES);

    prep_weights_kernel<<<256, 256>>>(W, U);
    zero_state_kernel<<<(BATCH * HID + 255) / 256, 256>>>();

    dim3 grid(HID / BHU, BATCH / BM);   // (16, 16) = 256 CTAs
    for (int t = 0; t < SEQT; t++) {
        lstm_step_kernel<<<grid, 256, SMEM_BYTES>>>(x, bias, t);
    }

    vae_head_kernel<<<BATCH, ZD>>>(eps, Wm, bm, Wv, bv, out);
}

// round 8
// speedup vs baseline: 2.9332x; 1.5330x over previous
#include <cuda_runtime.h>
#include <cstdint>

#define BATCH 1024
#define SEQT  256
#define DIN   128
#define HID   512
#define ZD    64
#define G4    2048   // 4*HID
#define KTOT  640    // DIN + HID

// ---------------- packed operand buffers ----------------
// Weights packed: [hb(16)][kc(80)][grp(4)][half(2)][slot(32)][4]
//   value = Wfull[k = kc*8 + qtr + 4*(w&1)][col = (2*half + (w>>1))*HID + hb*32 + grp*8 + qid]
//   (Wfull = W rows 0..127 then U rows 0..511), tf32-rounded. slot = qid*4+qtr.
__device__ float g_bp[16 * 80 * 4 * 2 * 32 * 4];      // 5.24 MB
// x packed: [mb(16)][t(256)][kc(16)][wm(2)][mt(2)][slot(32)][4]
//   value = x[b = mb*64 + wm*32 + mt*16 + qid + 8*(w&1)][t][k = kc*8 + qtr + 4*(w>>1)]
__device__ float g_xp[16 * 256 * 16 * 512];           // 134 MB
// h packed ping-pong: [buf(2)][mb(16)][kc(64)][wm(2)][mt(2)][slot(32)][4]
//   value = h[row = mb*64 + wm*32 + mt*16 + qid + 8*(w&1)][k = kc*8 + qtr + 4*(w>>1)]
__device__ float g_hp[2 * 16 * 64 * 512];             // 4 MB
__device__ float g_c[BATCH * HID];                    // cell state, normal layout

__device__ __forceinline__ float sigmoidf_(float v) {
    return 1.0f / (1.0f + __expf(-v));
}
__device__ __forceinline__ float softplusf_(float v) {
    return (v > 20.0f) ? v : log1pf(__expf(v));
}
__device__ __forceinline__ float f2tf32f(float f) {
    uint32_t r;
    asm("cvt.rna.tf32.f32 %0, %1;" : "=r"(r) : "f"(f));
    return __uint_as_float(r);
}
__device__ __forceinline__ void mma_tf32(float c[4], const float a[4], float b0, float b1) {
    asm volatile(
        "mma.sync.aligned.m16n8k8.row.col.f32.tf32.tf32.f32 "
        "{%0,%1,%2,%3}, {%4,%5,%6,%7}, {%8,%9}, {%0,%1,%2,%3};"
        : "+f"(c[0]), "+f"(c[1]), "+f"(c[2]), "+f"(c[3])
        : "r"(__float_as_uint(a[0])), "r"(__float_as_uint(a[1])),
          "r"(__float_as_uint(a[2])), "r"(__float_as_uint(a[3])),
          "r"(__float_as_uint(b0)), "r"(__float_as_uint(b1)));
}
__device__ __forceinline__ void cp16(float* dst, const float* src) {
    uint32_t d = (uint32_t)__cvta_generic_to_shared(dst);
    asm volatile("cp.async.cg.shared.global [%0], [%1], 16;" :: "r"(d), "l"(src));
}

// Tiling: CTA = 64(M) x 128(N), KT=32 (4 chunks of k8), 20 stages, 4-buffer ring
constexpr int NST     = 20;
constexpr int A_STAGE = 2048;               // floats: 4 chunks x 512
constexpr int B_STAGE = 4096;               // floats: 4 chunks x 1024
constexpr int BUF_FL  = A_STAGE + B_STAGE;  // 6144 floats per ring buffer
constexpr int SMEM_BYTES = 4 * BUF_FL * 4;  // 98304

// issue one K stage (32 k) into ring buffer (s & 3): pure linear 16B copies
__device__ __forceinline__ void issue_stage(float* smem, int s, int t, int mb, int hb, int tid) {
    const float* asrc = (s < 4)
        ? g_xp + (((size_t)(mb * 256 + t) * 16) + s * 4) * 512
        : g_hp + (((size_t)((t & 1) * 16 + mb) * 64) + (s * 4 - 16)) * 512;
    const float* bsrc = g_bp + ((size_t)hb * 80 + s * 4) * 1024;
    float* A = smem + (s & 3) * BUF_FL;
    float* B = A + A_STAGE;
#pragma unroll
    for (int i = 0; i < 2; i++) cp16(A + (i * 256 + tid) * 4, asrc + (i * 256 + tid) * 4);
#pragma unroll
    for (int i = 0; i < 4; i++) cp16(B + (i * 256 + tid) * 4, bsrc + (i * 256 + tid) * 4);
    asm volatile("cp.async.commit_group;" ::: "memory");
}

// grid: (16 hb, 16 mb) = 256 CTAs; 256 threads (8 warps: 2 M-halves x 4 N-groups)
__global__ __launch_bounds__(256, 2) void lstm_step_kernel(const float* __restrict__ bias, int t)
{
    extern __shared__ float smem[];
    const int hb = blockIdx.x;
    const int mb = blockIdx.y;
    const int tid = threadIdx.x;
    const int warp = tid >> 5;
    const int lane = tid & 31;
    const int wm = warp & 1;
    const int wn = warp >> 1;
    const int qid = lane >> 2;
    const int qtr = lane & 3;

    float acc[2][4][4];
#pragma unroll
    for (int mt = 0; mt < 2; mt++)
#pragma unroll
        for (int g = 0; g < 4; g++)
#pragma unroll
            for (int q = 0; q < 4; q++)
                acc[mt][g][q] = 0.0f;

    issue_stage(smem, 0, t, mb, hb, tid);
    issue_stage(smem, 1, t, mb, hb, tid);
    issue_stage(smem, 2, t, mb, hb, tid);

    for (int s = 0; s < NST; s++) {
        asm volatile("cp.async.wait_group 2;" ::: "memory");   // stage s landed
        __syncthreads();
        if (s + 3 < NST)
            issue_stage(smem, s + 3, t, mb, hb, tid);
        else
            asm volatile("cp.async.commit_group;" ::: "memory");  // keep group counts flowing

        const float* A = smem + (s & 3) * BUF_FL;
        const float* B = A + A_STAGE;
#pragma unroll
        for (int kc4 = 0; kc4 < 4; kc4++) {
            float4 a0 = *reinterpret_cast<const float4*>(A + kc4 * 512 + (wm * 2 + 0) * 128 + lane * 4);
            float4 a1 = *reinterpret_cast<const float4*>(A + kc4 * 512 + (wm * 2 + 1) * 128 + lane * 4);
            float4 b0 = *reinterpret_cast<const float4*>(B + kc4 * 1024 + (wn * 2 + 0) * 128 + lane * 4);
            float4 b1 = *reinterpret_cast<const float4*>(B + kc4 * 1024 + (wn * 2 + 1) * 128 + lane * 4);
            float af0[4] = {a0.x, a0.y, a0.z, a0.w};
            float af1[4] = {a1.x, a1.y, a1.z, a1.w};
            mma_tf32(acc[0][0], af0, b0.x, b0.y);
            mma_tf32(acc[0][1], af0, b0.z, b0.w);
            mma_tf32(acc[0][2], af0, b1.x, b1.y);
            mma_tf32(acc[0][3], af0, b1.z, b1.w);
            mma_tf32(acc[1][0], af1, b0.x, b0.y);
            mma_tf32(acc[1][1], af1, b0.z, b0.w);
            mma_tf32(acc[1][2], af1, b1.x, b1.y);
            mma_tf32(acc[1][3], af1, b1.z, b1.w);
        }
    }

    // ---- LSTM pointwise epilogue; h written in packed layout for next step / head
    const int hbuf = (t + 1) & 1;
#pragma unroll
    for (int mt = 0; mt < 2; mt++) {
#pragma unroll
        for (int half = 0; half < 2; half++) {
            int r = wm * 32 + mt * 16 + qid + half * 8;
            size_t coff = (size_t)(mb * 64 + r) * HID + hb * 32 + wn * 8 + qtr * 2;
            float2 c2 = *reinterpret_cast<float2*>(g_c + coff);
            float res[2];
#pragma unroll
            for (int u = 0; u < 2; u++) {
                int q  = half * 2 + u;
                int hh = hb * 32 + wn * 8 + qtr * 2 + u;
                float gi = acc[mt][0][q] + bias[hh];
                float gf = acc[mt][1][q] + bias[HID + hh];
                float gg = acc[mt][2][q] + bias[2 * HID + hh];
                float go = acc[mt][3][q] + bias[3 * HID + hh];
                float iv = sigmoidf_(gi);
                float fv = sigmoidf_(gf);
                float gv = softplusf_(gg);
                float ov = sigmoidf_(go);
                float cold = u ? c2.y : c2.x;
                float cn = fv * cold + iv * gv;
                if (u) c2.y = cn; else c2.x = cn;
                res[u] = f2tf32f(ov * softplusf_(cn));
            }
            *reinterpret_cast<float2*>(g_c + coff) = c2;
            // packed h dest: [hbuf][mb][kc = hb*4+wn][wm][mt][slot][w]
            size_t base = (((((size_t)(hbuf * 16 + mb)) * 64 + (hb * 4 + wn)) * 2 + wm) * 2 + mt) * 128;
#pragma unroll
            for (int u = 0; u < 2; u++) {
                int slot = qid * 4 + ((qtr * 2 + u) & 3);
                int w    = half + 2 * (qtr >> 1);
                g_hp[base + slot * 4 + w] = res[u];
            }
        }
    }
}

// ---- pack weights into fragment order (tf32-rounded); 81920 threads
__global__ void pack_w_kernel(const float* __restrict__ W, const float* __restrict__ U) {
    int idx = blockIdx.x * blockDim.x + threadIdx.x;
    if (idx >= 16 * 80 * 4 * 2 * 8) return;
    int qid = idx & 7;  idx >>= 3;
    int half = idx & 1; idx >>= 1;
    int grp = idx & 3;  idx >>= 2;
    int kc = idx % 80;
    int hb = idx / 80;
#pragma unroll
    for (int qtr = 0; qtr < 4; qtr++) {
        float v[4];
#pragma unroll
        for (int gg = 0; gg < 2; gg++) {
            int col = (2 * half + gg) * HID + hb * 32 + grp * 8 + qid;
#pragma unroll
            for (int p = 0; p < 2; p++) {
                int k = kc * 8 + qtr + 4 * p;
                float s = (k < DIN) ? W[(size_t)k * G4 + col]
                                    : U[(size_t)(k - DIN) * G4 + col];
                v[gg * 2 + p] = f2tf32f(s);
            }
        }
        float* dst = g_bp + ((((size_t)(hb * 80 + kc) * 4 + grp) * 2 + half) * 128) + (qid * 4 + qtr) * 4;
        *reinterpret_cast<float4*>(dst) = make_float4(v[0], v[1], v[2], v[3]);
    }
}

// ---- pack x into fragment order (tf32-rounded); 2,097,152 threads
__global__ void pack_x_kernel(const float* __restrict__ x) {
    int idx = blockIdx.x * blockDim.x + threadIdx.x;
    int qid = idx & 7;
    int mt  = (idx >> 3) & 1;
    int wm  = (idx >> 4) & 1;
    int kc  = (idx >> 5) & 15;
    int t   = (idx >> 9) & 255;
    int mb  = idx >> 17;
    if (mb >= 16) return;
    int m = mb * 64 + wm * 32 + mt * 16 + qid;
    const float* r0 = x + ((size_t)m * SEQT + t) * DIN + kc * 8;
    const float* r1 = x + ((size_t)(m + 8) * SEQT + t) * DIN + kc * 8;
    float4 f0 = *reinterpret_cast<const float4*>(r0);
    float4 f1 = *reinterpret_cast<const float4*>(r0 + 4);
    float4 g0 = *reinterpret_cast<const float4*>(r1);
    float4 g1 = *reinterpret_cast<const float4*>(r1 + 4);
    float a0[4] = {f0.x, f0.y, f0.z, f0.w};   // row m,   k 0..3
    float a1[4] = {f1.x, f1.y, f1.z, f1.w};   // row m,   k 4..7
    float b0[4] = {g0.x, g0.y, g0.z, g0.w};   // row m+8, k 0..3
    float b1[4] = {g1.x, g1.y, g1.z, g1.w};   // row m+8, k 4..7
    float* dst = g_xp + (((size_t)(mb * 256 + t) * 16 + kc) * 512)
                      + (wm * 2 + mt) * 128 + qid * 16;
#pragma unroll
    for (int qtr = 0; qtr < 4; qtr++) {
        *reinterpret_cast<float4*>(dst + qtr * 4) =
            make_float4(f2tf32f(a0[qtr]), f2tf32f(b0[qtr]), f2tf32f(a1[qtr]), f2tf32f(b1[qtr]));
    }
}

__global__ void zero_state_kernel() {
    int i = blockIdx.x * blockDim.x + threadIdx.x;
    if (i < BATCH * HID) {
        g_hp[i] = 0.0f;   // buf 0, read at t=0
        g_c[i]  = 0.0f;
    }
}

// Final h is in g_hp buf 0 (t=255 writes (255+1)&1 = 0). Head: stage h into smem, fp32 math.
__global__ void vae_head_kernel(
    const float* __restrict__ eps,
    const float* __restrict__ Wm, const float* __restrict__ bm,
    const float* __restrict__ Wv, const float* __restrict__ bv,
    float* __restrict__ out)
{
    __shared__ float hs[HID];
    int b = blockIdx.x;
    int z = threadIdx.x;
    int mb = b >> 6, r = b & 63;
    int wm = r >> 5, mt = (r >> 4) & 1, half = (r >> 3) & 1, qid = r & 7;
    size_t rowbase = ((((size_t)mb * 64) * 2) * 2) * 128;   // buf 0, mb base (kc folded below)
    // cooperative load of this row's 512 h values
    for (int k = z; k < HID; k += ZD) {
        int kc = k >> 3, qtr = k & 3, p = (k >> 2) & 1;
        size_t idx = ((((size_t)mb * 64 + kc) * 2 + wm) * 2 + mt) * 128 + (qid * 4 + qtr) * 4 + half + 2 * p;
        hs[k] = g_hp[idx];
    }
    (void)rowbase;
    __syncthreads();
    float am = 0.0f, av = 0.0f;
#pragma unroll 8
    for (int k = 0; k < HID; k++) {
        float hv = hs[k];
        am = fmaf(hv, Wm[(size_t)k * ZD + z], am);
        av = fmaf(hv, Wv[(size_t)k * ZD + z], av);
    }
    float mu = am + bm[z];
    float lv = av + bv[z];
    size_t o = (size_t)b * ZD + z;
    out[o]                          = mu;
    out[(size_t)BATCH * ZD + o]     = lv;
    out[2 * (size_t)BATCH * ZD + o] = mu + eps[o] * __expf(0.5f * lv);
}

extern "C" void kernel_launch(void* const* d_in, const int* in_sizes, int n_in,
                              void* d_out, int out_size)
{
    const float* x    = (const float*)d_in[0];
    const float* eps  = (const float*)d_in[1];
    const float* W    = (const float*)d_in[2];
    const float* U    = (const float*)d_in[3];
    const float* bias = (const float*)d_in[4];
    const float* Wm   = (const float*)d_in[5];
    const float* bm   = (const float*)d_in[6];
    const float* Wv   = (const float*)d_in[7];
    const float* bv   = (const float*)d_in[8];
    float* out = (float*)d_out;

    cudaFuncSetAttribute(lstm_step_kernel,
                         cudaFuncAttributeMaxDynamicSharedMemorySize, SMEM_BYTES);

    pack_w_kernel<<<320, 256>>>(W, U);
    pack_x_kernel<<<8192, 256>>>(x);
    zero_state_kernel<<<(BATCH * HID + 255) / 256, 256>>>();

    dim3 grid(16, 16);   // (hb, mb) = 256 CTAs
    for (int t = 0; t < SEQT; t++) {
        lstm_step_kernel<<<grid, 256, SMEM_BYTES>>>(bias, t);
    }

    vae_head_kernel<<<BATCH, ZD>>>(eps, Wm, bm, Wv, bv, out);
}

// round 9
// speedup vs baseline: 3.1719x; 1.0814x over previous
#include <cuda_runtime.h>
#include <cuda_fp16.h>
#include <cstdint>

#define BATCH 1024
#define SEQT  256
#define DIN   128
#define HID   512
#define ZD    64
#define G4    2048   // 4*HID
#define KTOT  640    // DIN + HID

// ---------------- packed fp16 operand buffers (mma.m16n8k16 fragment order) ----------------
// B (weights): [hb(16)][kc(40)][wn(4)][gp(2)][lane(32)][4 x half2]
//   lane entry 16B = {g=2gp b0, g=2gp b1, g=2gp+1 b0, g=2gp+1 b1}
//   b0 = (k = kc*16 + qtr*2 +{0,1}, col), b1 = k+8; col = g*HID + hb*32 + wn*8 + qid
__device__ __half g_wp[16 * 40 * 4 * 2 * 32 * 8];          // 2.62 MB
// A (x): [mb(16)][t(256)][kc(8)][wm(2)][mt(2)][lane(32)][4 x half2]
//   reg0 = (row base+qid,   k = kc*16+2qtr,+1), reg1 = row+8 same k, reg2 = row, k+8, reg3 = row+8, k+8
__device__ __half g_xp[16 * 256 * 8 * 2 * 2 * 32 * 8];     // 67 MB
// A (h) ping-pong: [buf(2)][mb(16)][kc(32)][wm(2)][mt(2)][lane(32)][4 x half2]
__device__ __half g_hp[2 * 16 * 32 * 2 * 2 * 32 * 8];      // 2 MB
__device__ float  g_c[BATCH * HID];                        // cell state fp32

__device__ __forceinline__ float sigmoidf_(float v) {
    return 1.0f / (1.0f + __expf(-v));
}
__device__ __forceinline__ float softplusf_(float v) {
    return (v > 20.0f) ? v : log1pf(__expf(v));
}
__device__ __forceinline__ void mma_f16(float c[4], const uint4& a, uint32_t b0, uint32_t b1) {
    asm volatile(
        "mma.sync.aligned.m16n8k16.row.col.f32.f16.f16.f32 "
        "{%0,%1,%2,%3}, {%4,%5,%6,%7}, {%8,%9}, {%0,%1,%2,%3};"
        : "+f"(c[0]), "+f"(c[1]), "+f"(c[2]), "+f"(c[3])
        : "r"(a.x), "r"(a.y), "r"(a.z), "r"(a.w), "r"(b0), "r"(b1));
}
__device__ __forceinline__ void cp16(void* dst, const void* src) {
    uint32_t d = (uint32_t)__cvta_generic_to_shared(dst);
    asm volatile("cp.async.cg.shared.global [%0], [%1], 16;" :: "r"(d), "l"(src));
}

// Stage = 64 k = 4 k16-chunks. 10 stages. Ring of 4 buffers.
constexpr int NST      = 10;
constexpr int A_BYTES  = 4 * 2048;            // 8 KB  (4 chunks x [wm][mt][lane][16B])
constexpr int B_BYTES  = 4 * 4096;            // 16 KB (4 chunks x [wn][gp][lane][16B])
constexpr int BUF_BYTES = A_BYTES + B_BYTES;  // 24 KB
constexpr int SMEM_BYTES = 4 * BUF_BYTES;     // 96 KB

__device__ __forceinline__ void issue_stage(char* smem, int s, int t, int mb, int hb, int tid) {
    // A source: stages 0-1 from x (chunks s*4), stages 2-9 from h (chunks s*4-8)
    const char* asrc = (s < 2)
        ? (const char*)(g_xp + ((size_t)((mb * 256 + t) * 8) + s * 4) * 1024)
        : (const char*)(g_hp + ((size_t)(((t & 1) * 16 + mb) * 32) + (s * 4 - 8)) * 1024);
    const char* bsrc = (const char*)(g_wp + ((size_t)(hb * 40) + s * 4) * 2048);
    char* A = smem + (s & 3) * BUF_BYTES;
    char* B = A + A_BYTES;
#pragma unroll
    for (int i = 0; i < 2; i++) cp16(A + (i * 256 + tid) * 16, asrc + (i * 256 + tid) * 16);
#pragma unroll
    for (int i = 0; i < 4; i++) cp16(B + (i * 256 + tid) * 16, bsrc + (i * 256 + tid) * 16);
    asm volatile("cp.async.commit_group;" ::: "memory");
}

// grid: (16 hb, 16 mb) = 256 CTAs; 256 threads = 8 warps (2 wm x 4 wn)
__global__ __launch_bounds__(256, 2) void lstm_step_kernel(const float* __restrict__ bias, int t)
{
    extern __shared__ char smem[];
    const int hb = blockIdx.x;
    const int mb = blockIdx.y;
    const int tid = threadIdx.x;
    const int warp = tid >> 5;
    const int lane = tid & 31;
    const int wm = warp & 1;
    const int wn = warp >> 1;
    const int qid = lane >> 2;
    const int qtr = lane & 3;

    float acc[2][4][4];
#pragma unroll
    for (int mt = 0; mt < 2; mt++)
#pragma unroll
        for (int g = 0; g < 4; g++)
#pragma unroll
            for (int q = 0; q < 4; q++)
                acc[mt][g][q] = 0.0f;

    issue_stage(smem, 0, t, mb, hb, tid);
    issue_stage(smem, 1, t, mb, hb, tid);
    issue_stage(smem, 2, t, mb, hb, tid);

    for (int s = 0; s < NST; s++) {
        asm volatile("cp.async.wait_group 2;" ::: "memory");
        __syncthreads();
        if (s + 3 < NST)
            issue_stage(smem, s + 3, t, mb, hb, tid);
        else
            asm volatile("cp.async.commit_group;" ::: "memory");

        const char* A = smem + (s & 3) * BUF_BYTES;
        const char* B = A + A_BYTES;
#pragma unroll
        for (int c = 0; c < 4; c++) {
            uint4 a0 = *reinterpret_cast<const uint4*>(A + c * 2048 + (wm * 2 + 0) * 512 + lane * 16);
            uint4 a1 = *reinterpret_cast<const uint4*>(A + c * 2048 + (wm * 2 + 1) * 512 + lane * 16);
            uint4 b0 = *reinterpret_cast<const uint4*>(B + c * 4096 + (wn * 2 + 0) * 512 + lane * 16);
            uint4 b1 = *reinterpret_cast<const uint4*>(B + c * 4096 + (wn * 2 + 1) * 512 + lane * 16);
            mma_f16(acc[0][0], a0, b0.x, b0.y);
            mma_f16(acc[0][1], a0, b0.z, b0.w);
            mma_f16(acc[0][2], a0, b1.x, b1.y);
            mma_f16(acc[0][3], a0, b1.z, b1.w);
            mma_f16(acc[1][0], a1, b0.x, b0.y);
            mma_f16(acc[1][1], a1, b0.z, b0.w);
            mma_f16(acc[1][2], a1, b1.x, b1.y);
            mma_f16(acc[1][3], a1, b1.z, b1.w);
        }
    }

    // ---- LSTM pointwise epilogue; h written as packed fp16 fragments for next step
    const int hbuf = (t + 1) & 1;
    const int kc_h  = hb * 2 + (wn >> 1);     // hidden chunk this thread's hh pair lives in
    const int reg_k = 2 * (wn & 1);           // +0/+1 selected by row half below
    const int lane_p = qid * 4 + qtr;
#pragma unroll
    for (int mt = 0; mt < 2; mt++) {
#pragma unroll
        for (int half = 0; half < 2; half++) {
            int r = wm * 32 + mt * 16 + qid + half * 8;
            size_t coff = (size_t)(mb * 64 + r) * HID + hb * 32 + wn * 8 + qtr * 2;
            float2 c2 = *reinterpret_cast<float2*>(g_c + coff);
            float res[2];
#pragma unroll
            for (int u = 0; u < 2; u++) {
                int q  = half * 2 + u;
                int hh = hb * 32 + wn * 8 + qtr * 2 + u;
                float gi = acc[mt][0][q] + bias[hh];
                float gf = acc[mt][1][q] + bias[HID + hh];
                float gg = acc[mt][2][q] + bias[2 * HID + hh];
                float go = acc[mt][3][q] + bias[3 * HID + hh];
                float iv = sigmoidf_(gi);
                float fv = sigmoidf_(gf);
                float gv = softplusf_(gg);
                float ov = sigmoidf_(go);
                float cold = u ? c2.y : c2.x;
                float cn = fv * cold + iv * gv;
                if (u) c2.y = cn; else c2.x = cn;
                res[u] = ov * softplusf_(cn);
            }
            *reinterpret_cast<float2*>(g_c + coff) = c2;
            size_t off = ((((((size_t)(hbuf * 16 + mb)) * 32 + kc_h) * 2 + wm) * 2 + mt) * 32 + lane_p) * 8
                         + (size_t)(half + reg_k) * 2;
            *reinterpret_cast<__half2*>(g_hp + off) = __floats2half2_rn(res[0], res[1]);
        }
    }
}

// ---- pack weights into fp16 fragment order; 163840 threads
__global__ void pack_w_kernel(const float* __restrict__ W, const float* __restrict__ U) {
    int idx = blockIdx.x * blockDim.x + threadIdx.x;
    if (idx >= 16 * 40 * 4 * 2 * 32) return;
    int lane = idx & 31;
    int gp   = (idx >> 5) & 1;
    int wn   = (idx >> 6) & 3;
    int rest = idx >> 8;
    int kc = rest % 40;
    int hb = rest / 40;
    int qid = lane >> 2, qtr = lane & 3;
    __half2 h2[4];
#pragma unroll
    for (int g2 = 0; g2 < 2; g2++) {
        int col = (gp * 2 + g2) * HID + hb * 32 + wn * 8 + qid;
#pragma unroll
        for (int hi = 0; hi < 2; hi++) {
            int k = kc * 16 + qtr * 2 + hi * 8;
            float v0 = (k     < DIN) ? W[(size_t)k * G4 + col]       : U[(size_t)(k - DIN) * G4 + col];
            float v1 = (k + 1 < DIN) ? W[(size_t)(k + 1) * G4 + col] : U[(size_t)(k + 1 - DIN) * G4 + col];
            h2[g2 * 2 + hi] = __floats2half2_rn(v0, v1);
        }
    }
    __half* dst = g_wp + ((((size_t)(hb * 40 + kc) * 4 + wn) * 2 + gp) * 32 + lane) * 8;
    *reinterpret_cast<uint4*>(dst) = *reinterpret_cast<uint4*>(h2);
}

// ---- pack x into fp16 fragment order; 4,194,304 threads
__global__ void pack_x_kernel(const float* __restrict__ x) {
    int idx = blockIdx.x * blockDim.x + threadIdx.x;
    int lane = idx & 31;
    int mt = (idx >> 5) & 1;
    int wm = (idx >> 6) & 1;
    int kc = (idx >> 7) & 7;
    int t  = (idx >> 10) & 255;
    int mb = idx >> 18;
    if (mb >= 16) return;
    int qid = lane >> 2, qtr = lane & 3;
    int row0 = mb * 64 + wm * 32 + mt * 16 + qid;
    int k0 = kc * 16 + qtr * 2;
    const float* p0 = x + ((size_t)row0 * SEQT + t) * DIN + k0;
    const float* p1 = x + ((size_t)(row0 + 8) * SEQT + t) * DIN + k0;
    float2 r0lo = *reinterpret_cast<const float2*>(p0);
    float2 r1lo = *reinterpret_cast<const float2*>(p1);
    float2 r0hi = *reinterpret_cast<const float2*>(p0 + 8);
    float2 r1hi = *reinterpret_cast<const float2*>(p1 + 8);
    __half2 h2[4];
    h2[0] = __floats2half2_rn(r0lo.x, r0lo.y);
    h2[1] = __floats2half2_rn(r1lo.x, r1lo.y);
    h2[2] = __floats2half2_rn(r0hi.x, r0hi.y);
    h2[3] = __floats2half2_rn(r1hi.x, r1hi.y);
    __half* dst = g_xp + (((((size_t)(mb * 256 + t) * 8 + kc) * 2 + wm) * 2 + mt) * 32 + lane) * 8;
    *reinterpret_cast<uint4*>(dst) = *reinterpret_cast<uint4*>(h2);
}

__global__ void zero_state_kernel() {
    int i = blockIdx.x * blockDim.x + threadIdx.x;
    if (i < BATCH * HID) {
        g_c[i] = 0.0f;
        g_hp[i] = __float2half(0.0f);           // buf 0 (read at t=0)
    }
}

// Final h in g_hp buf 0. Head: unpack row's 512 h values into smem, fp32 math.
__global__ void vae_head_kernel(
    const float* __restrict__ eps,
    const float* __restrict__ Wm, const float* __restrict__ bm,
    const float* __restrict__ Wv, const float* __restrict__ bv,
    float* __restrict__ out)
{
    __shared__ float hs[HID];
    int b = blockIdx.x;
    int z = threadIdx.x;
    int mb = b >> 6, r6 = b & 63;
    int wm = (r6 >> 5) & 1, mt = (r6 >> 4) & 1, rh = (r6 >> 3) & 1, qid = r6 & 7;
    for (int k = z; k < HID; k += ZD) {
        int kc = k >> 4, koff = k & 15;
        int hi8 = koff >> 3, qtr = (koff >> 1) & 3, v = koff & 1;
        int lane = qid * 4 + qtr;
        int reg = rh + 2 * hi8;
        size_t off = ((((((size_t)mb) * 32 + kc) * 2 + wm) * 2 + mt) * 32 + lane) * 8 + reg * 2 + v;
        hs[k] = __half2float(g_hp[off]);
    }
    __syncthreads();
    float am = 0.0f, av = 0.0f;
#pragma unroll 8
    for (int k = 0; k < HID; k++) {
        float hv = hs[k];
        am = fmaf(hv, Wm[(size_t)k * ZD + z], am);
        av = fmaf(hv, Wv[(size_t)k * ZD + z], av);
    }
    float mu = am + bm[z];
    float lv = av + bv[z];
    size_t o = (size_t)b * ZD + z;
    out[o]                          = mu;
    out[(size_t)BATCH * ZD + o]     = lv;
    out[2 * (size_t)BATCH * ZD + o] = mu + eps[o] * __expf(0.5f * lv);
}

extern "C" void kernel_launch(void* const* d_in, const int* in_sizes, int n_in,
                              void* d_out, int out_size)
{
    const float* x    = (const float*)d_in[0];
    const float* eps  = (const float*)d_in[1];
    const float* W    = (const float*)d_in[2];
    const float* U    = (const float*)d_in[3];
    const float* bias = (const float*)d_in[4];
    const float* Wm   = (const float*)d_in[5];
    const float* bm   = (const float*)d_in[6];
    const float* Wv   = (const float*)d_in[7];
    const float* bv   = (const float*)d_in[8];
    float* out = (float*)d_out;

    cudaFuncSetAttribute(lstm_step_kernel,
                         cudaFuncAttributeMaxDynamicSharedMemorySize, SMEM_BYTES);

    pack_w_kernel<<<640, 256>>>(W, U);
    pack_x_kernel<<<16384, 256>>>(x);
    zero_state_kernel<<<(BATCH * HID + 255) / 256, 256>>>();

    dim3 grid(16, 16);   // (hb, mb)
    for (int t = 0; t < SEQT; t++) {
        lstm_step_kernel<<<grid, 256, SMEM_BYTES>>>(bias, t);
    }

    vae_head_kernel<<<BATCH, ZD>>>(eps, Wm, bm, Wv, bv, out);
}

// round 11
// speedup vs baseline: 5.3480x; 1.6861x over previous
#include <cuda_runtime.h>
#include <cuda_fp16.h>
#include <cstdint>

#define BATCH 1024
#define SEQT  256
#define DIN   128
#define HID   512
#define ZD    64
#define G4    2048   // 4*HID

// ---------------- packed fp16 operand buffers (mma.m16n8k16 fragment order) ----------------
// Weights: [hb(16)][kc(40)][wn(4)][gp(2)][lane(32)][8 halves]  (same layout as R9)
__device__ __half g_wp[16 * 40 * 4 * 2 * 32 * 8];          // 2.62 MB
// x: [mb(8)][t(256)][kc(8)][mtile(8)][lane(32)][8 halves]
__device__ __half g_xp[8 * 256 * 8 * 8 * 32 * 8];          // 67 MB
// h ping-pong: [buf(2)][mb(8)][kc(32)][mtile(8)][lane(32)][8 halves]
__device__ __half g_hp[2 * 8 * 32 * 8 * 32 * 8];           // 2 MB
// per-mb barrier state (128B stride to avoid false sharing)
__device__ unsigned          g_bcnt[8 * 32];
__device__ volatile unsigned g_bgen[8 * 32];

__device__ __forceinline__ float sigmoidf_(float v) {
    return 1.0f / (1.0f + __expf(-v));
}
__device__ __forceinline__ float softplusf_(float v) {
    return (v > 20.0f) ? v : log1pf(__expf(v));
}
__device__ __forceinline__ void mma_f16(float c[4], const uint4& a, uint32_t b0, uint32_t b1) {
    asm volatile(
        "mma.sync.aligned.m16n8k16.row.col.f32.f16.f16.f32 "
        "{%0,%1,%2,%3}, {%4,%5,%6,%7}, {%8,%9}, {%0,%1,%2,%3};"
        : "+f"(c[0]), "+f"(c[1]), "+f"(c[2]), "+f"(c[3])
        : "r"(a.x), "r"(a.y), "r"(a.z), "r"(a.w), "r"(b0), "r"(b1));
}
__device__ __forceinline__ uint4 ldg_cg_128(const void* p) {
    uint4 v;
    asm volatile("ld.global.cg.v4.u32 {%0,%1,%2,%3}, [%4];"
                 : "=r"(v.x), "=r"(v.y), "=r"(v.z), "=r"(v.w) : "l"(p));
    return v;
}
__device__ __forceinline__ uint32_t h2_bits(__half2 h) {
    uint32_t u;
    memcpy(&u, &h, 4);
    return u;
}

constexpr int SMEM_BYTES = 40 * 4096;   // 160 KB: B slice [kc40][wn4][gp2][lane32][16B]

// ---- persistent kernel: grid (16 hb, 8 mb), 512 threads = 16 warps (4 wm x 4 wn)
__global__ __launch_bounds__(512, 1) void lstm_persist_kernel(const float* __restrict__ bias)
{
    extern __shared__ char sB[];
    const int hb  = blockIdx.x;
    const int mb  = blockIdx.y;
    const int tid = threadIdx.x;
    const int wid = tid >> 5;
    const int lane = tid & 31;
    const int wn = wid & 3;
    const int wm = wid >> 2;      // 0..3 -> mtiles {2wm, 2wm+1}
    const int qid = lane >> 2;
    const int qtr = lane & 3;

    // load persistent B slice into smem (once)
    {
        const uint4* src = reinterpret_cast<const uint4*>(g_wp) + (size_t)hb * (SMEM_BYTES / 16);
        uint4* dst = reinterpret_cast<uint4*>(sB);
        for (int i = tid; i < SMEM_BYTES / 16; i += 512) dst[i] = src[i];
    }
    // bias in registers (gates of this thread's two hidden units)
    float bs[4][2];
#pragma unroll
    for (int g = 0; g < 4; g++)
#pragma unroll
        for (int u = 0; u < 2; u++)
            bs[g][u] = bias[g * HID + hb * 32 + wn * 8 + qtr * 2 + u];

    float creg[2][2][2];   // cell state in registers: [mt][half][u]
#pragma unroll
    for (int mt = 0; mt < 2; mt++)
#pragma unroll
        for (int h = 0; h < 2; h++)
#pragma unroll
            for (int u = 0; u < 2; u++)
                creg[mt][h][u] = 0.0f;

    __syncthreads();
    unsigned gen = g_bgen[mb * 32];

    const int kc_h  = hb * 2 + (wn >> 1);
    const int khalf = wn & 1;

    for (int t = 0; t < SEQT; t++) {
        float acc[2][4][4];
#pragma unroll
        for (int mt = 0; mt < 2; mt++)
#pragma unroll
            for (int g = 0; g < 4; g++)
#pragma unroll
                for (int q = 0; q < 4; q++)
                    acc[mt][g][q] = 0.0f;

        // ---- x chunks (kc 0..7): regular LDG (x is read-only)
        {
            const uint4* ax = reinterpret_cast<const uint4*>(
                g_xp + ((size_t)(mb * 256 + t) * 8) * 2048);
#pragma unroll
            for (int kc = 0; kc < 8; kc++) {
                uint4 a0 = ax[(size_t)kc * 256 + (wm * 2 + 0) * 32 + lane];
                uint4 a1 = ax[(size_t)kc * 256 + (wm * 2 + 1) * 32 + lane];
                const uint4* bp = reinterpret_cast<const uint4*>(
                    sB + kc * 4096 + (wn * 2) * 512 + lane * 16);
                uint4 b0 = bp[0];
                uint4 b1 = bp[32];
                mma_f16(acc[0][0], a0, b0.x, b0.y);
                mma_f16(acc[0][1], a0, b0.z, b0.w);
                mma_f16(acc[0][2], a0, b1.x, b1.y);
                mma_f16(acc[0][3], a0, b1.z, b1.w);
                mma_f16(acc[1][0], a1, b0.x, b0.y);
                mma_f16(acc[1][1], a1, b0.z, b0.w);
                mma_f16(acc[1][2], a1, b1.x, b1.y);
                mma_f16(acc[1][3], a1, b1.z, b1.w);
            }
        }
        // ---- h chunks (kc 8..39): L2 loads (bypass L1 — producers are other SMs)
        if (t > 0) {
            const __half* ah = g_hp + ((size_t)((t & 1) * 8 + mb) * 32) * 2048;
#pragma unroll 8
            for (int kc = 0; kc < 32; kc++) {
                uint4 a0 = ldg_cg_128(ah + ((size_t)kc * 8 + wm * 2 + 0) * 256 + lane * 8);
                uint4 a1 = ldg_cg_128(ah + ((size_t)kc * 8 + wm * 2 + 1) * 256 + lane * 8);
                const uint4* bp = reinterpret_cast<const uint4*>(
                    sB + (kc + 8) * 4096 + (wn * 2) * 512 + lane * 16);
                uint4 b0 = bp[0];
                uint4 b1 = bp[32];
                mma_f16(acc[0][0], a0, b0.x, b0.y);
                mma_f16(acc[0][1], a0, b0.z, b0.w);
                mma_f16(acc[0][2], a0, b1.x, b1.y);
                mma_f16(acc[0][3], a0, b1.z, b1.w);
                mma_f16(acc[1][0], a1, b0.x, b0.y);
                mma_f16(acc[1][1], a1, b0.z, b0.w);
                mma_f16(acc[1][2], a1, b1.x, b1.y);
                mma_f16(acc[1][3], a1, b1.z, b1.w);
            }
        }

        // ---- LSTM epilogue: c in regs, h written as packed fragments (8B per mt)
        const int hbuf = (t + 1) & 1;
#pragma unroll
        for (int mt = 0; mt < 2; mt++) {
            float res[2][2];   // [half][u]
#pragma unroll
            for (int half = 0; half < 2; half++) {
#pragma unroll
                for (int u = 0; u < 2; u++) {
                    int q = half * 2 + u;
                    float gi = acc[mt][0][q] + bs[0][u];
                    float gf = acc[mt][1][q] + bs[1][u];
                    float gg = acc[mt][2][q] + bs[2][u];
                    float go = acc[mt][3][q] + bs[3][u];
                    float iv = sigmoidf_(gi);
                    float fv = sigmoidf_(gf);
                    float gv = softplusf_(gg);
                    float ov = sigmoidf_(go);
                    float cn = fv * creg[mt][half][u] + iv * gv;
                    creg[mt][half][u] = cn;
                    res[half][u] = ov * softplusf_(cn);
                }
            }
            __half2 r0 = __floats2half2_rn(res[0][0], res[0][1]);
            __half2 r1 = __floats2half2_rn(res[1][0], res[1][1]);
            size_t off = (((size_t)(hbuf * 8 + mb) * 32 + kc_h) * 8 + (wm * 2 + mt)) * 256
                         + (size_t)(qid * 4 + qtr) * 8 + khalf * 4;
            uint2 val;
            val.x = h2_bits(r0);
            val.y = h2_bits(r1);
            *reinterpret_cast<uint2*>(g_hp + off) = val;   // 8B store
        }

        // ---- per-mb barrier (16 CTAs share this batch slice)
        __threadfence();
        __syncthreads();
        if (tid == 0) {
            unsigned ticket = atomicAdd(&g_bcnt[mb * 32], 1u);
            if (ticket == 15u) {
                atomicExch(&g_bcnt[mb * 32], 0u);
                __threadfence();
                g_bgen[mb * 32] = gen + 1u;
            } else {
                while (g_bgen[mb * 32] == gen) __nanosleep(32);
            }
        }
        __syncthreads();
        gen = gen + 1u;
        __threadfence();
    }
}

// ---- pack weights into fp16 fragment order (unchanged layout from R9)
__global__ void pack_w_kernel(const float* __restrict__ W, const float* __restrict__ U) {
    int idx = blockIdx.x * blockDim.x + threadIdx.x;
    if (idx >= 16 * 40 * 4 * 2 * 32) return;
    int lane = idx & 31;
    int gp   = (idx >> 5) & 1;
    int wn   = (idx >> 6) & 3;
    int rest = idx >> 8;
    int kc = rest % 40;
    int hb = rest / 40;
    int qid = lane >> 2, qtr = lane & 3;
    __half2 h2[4];
#pragma unroll
    for (int g2 = 0; g2 < 2; g2++) {
        int col = (gp * 2 + g2) * HID + hb * 32 + wn * 8 + qid;
#pragma unroll
        for (int hi = 0; hi < 2; hi++) {
            int k = kc * 16 + qtr * 2 + hi * 8;
            float v0 = (k     < DIN) ? W[(size_t)k * G4 + col]       : U[(size_t)(k - DIN) * G4 + col];
            float v1 = (k + 1 < DIN) ? W[(size_t)(k + 1) * G4 + col] : U[(size_t)(k + 1 - DIN) * G4 + col];
            h2[g2 * 2 + hi] = __floats2half2_rn(v0, v1);
        }
    }
    __half* dst = g_wp + ((((size_t)(hb * 40 + kc) * 4 + wn) * 2 + gp) * 32 + lane) * 8;
    *reinterpret_cast<uint4*>(dst) = *reinterpret_cast<uint4*>(h2);
}

// ---- pack x into fp16 fragment order: [mb8][t][kc8][mtile8][lane][8]
__global__ void pack_x_kernel(const float* __restrict__ x) {
    int idx = blockIdx.x * blockDim.x + threadIdx.x;
    int lane  = idx & 31;
    int mtile = (idx >> 5) & 7;
    int kc    = (idx >> 8) & 7;
    int t     = (idx >> 11) & 255;
    int mb    = idx >> 19;
    if (mb >= 8) return;
    int qid = lane >> 2, qtr = lane & 3;
    int row0 = mb * 128 + mtile * 16 + qid;
    int k0 = kc * 16 + qtr * 2;
    const float* p0 = x + ((size_t)row0 * SEQT + t) * DIN + k0;
    const float* p1 = x + ((size_t)(row0 + 8) * SEQT + t) * DIN + k0;
    __half2 h2[4];
    h2[0] = __floats2half2_rn(p0[0], p0[1]);
    h2[1] = __floats2half2_rn(p1[0], p1[1]);
    h2[2] = __floats2half2_rn(p0[8], p0[9]);
    h2[3] = __floats2half2_rn(p1[8], p1[9]);
    __half* dst = g_xp + ((((size_t)(mb * 256 + t) * 8 + kc) * 8 + mtile) * 32 + lane) * 8;
    *reinterpret_cast<uint4*>(dst) = *reinterpret_cast<uint4*>(h2);
}

// ---- head: final h is g_hp buf 0 ((255+1)&1 == 0)
__global__ void vae_head_kernel(
    const float* __restrict__ eps,
    const float* __restrict__ Wm, const float* __restrict__ bm,
    const float* __restrict__ Wv, const float* __restrict__ bv,
    float* __restrict__ out)
{
    __shared__ float hs[HID];
    int b = blockIdx.x;
    int z = threadIdx.x;
    int mb = b >> 7, r = b & 127;
    int mtile = r >> 4, qid = r & 7, half = (r >> 3) & 1;
    for (int k = z; k < HID; k += ZD) {
        int kc = k >> 4, kin = k & 15;
        int kh = kin >> 3, qtr = (kin >> 1) & 3, u = kin & 1;
        size_t off = (((size_t)mb * 32 + kc) * 8 + mtile) * 256
                     + (size_t)(qid * 4 + qtr) * 8 + (half + 2 * kh) * 2 + u;
        hs[k] = __half2float(g_hp[off]);
    }
    __syncthreads();
    float am = 0.0f, av = 0.0f;
#pragma unroll 8
    for (int k = 0; k < HID; k++) {
        float hv = hs[k];
        am = fmaf(hv, Wm[(size_t)k * ZD + z], am);
        av = fmaf(hv, Wv[(size_t)k * ZD + z], av);
    }
    float mu = am + bm[z];
    float lv = av + bv[z];
    size_t o = (size_t)b * ZD + z;
    out[o]                          = mu;
    out[(size_t)BATCH * ZD + o]     = lv;
    out[2 * (size_t)BATCH * ZD + o] = mu + eps[o] * __expf(0.5f * lv);
}

extern "C" void kernel_launch(void* const* d_in, const int* in_sizes, int n_in,
                              void* d_out, int out_size)
{
    const float* x    = (const float*)d_in[0];
    const float* eps  = (const float*)d_in[1];
    const float* W    = (const float*)d_in[2];
    const float* U    = (const float*)d_in[3];
    const float* bias = (const float*)d_in[4];
    const float* Wm   = (const float*)d_in[5];
    const float* bm   = (const float*)d_in[6];
    const float* Wv   = (const float*)d_in[7];
    const float* bv   = (const float*)d_in[8];
    float* out = (float*)d_out;

    cudaFuncSetAttribute(lstm_persist_kernel,
                         cudaFuncAttributeMaxDynamicSharedMemorySize, SMEM_BYTES);

    pack_w_kernel<<<640, 256>>>(W, U);
    pack_x_kernel<<<16384, 256>>>(x);

    lstm_persist_kernel<<<dim3(16, 8), 512, SMEM_BYTES>>>(bias);

    vae_head_kernel<<<BATCH, ZD>>>(eps, Wm, bm, Wv, bv, out);
}

// round 12
// speedup vs baseline: 5.4001x; 1.0097x over previous
#include <cuda_runtime.h>
#include <cuda_fp16.h>
#include <cstdint>

#define BATCH 1024
#define SEQT  256
#define DIN   128
#define HID   512
#define ZD    64
#define G4    2048   // 4*HID

// ---------------- packed fp16 operand buffers (mma.m16n8k16 fragment order) ----------------
// Weights: [hb(16)][kc(40)][wn(4)][gp(2)][lane(32)][8 halves]
__device__ __half g_wp[16 * 40 * 4 * 2 * 32 * 8];          // 2.62 MB
// x: [mb(8)][t(256)][kc(8)][mtile(8)][lane(32)][8 halves]
__device__ __half g_xp[8 * 256 * 8 * 8 * 32 * 8];          // 67 MB
// h ping-pong: [buf(2)][mb(8)][kc(32)][mtile(8)][lane(32)][8 halves]
__device__ __half g_hp[2 * 8 * 32 * 8 * 32 * 8];           // 2 MB
// per-mb barrier state (128B stride)
__device__ unsigned          g_bcnt[8 * 32];
__device__ volatile unsigned g_bgen[8 * 32];

__device__ __forceinline__ float sigmoidf_(float v) {
    return 1.0f / (1.0f + __expf(-v));
}
__device__ __forceinline__ float softplusf_(float v) {
    return (v > 20.0f) ? v : log1pf(__expf(v));
}
__device__ __forceinline__ void mma_f16(float c[4], const uint4& a, uint32_t b0, uint32_t b1) {
    asm volatile(
        "mma.sync.aligned.m16n8k16.row.col.f32.f16.f16.f32 "
        "{%0,%1,%2,%3}, {%4,%5,%6,%7}, {%8,%9}, {%0,%1,%2,%3};"
        : "+f"(c[0]), "+f"(c[1]), "+f"(c[2]), "+f"(c[3])
        : "r"(a.x), "r"(a.y), "r"(a.z), "r"(a.w), "r"(b0), "r"(b1));
}
__device__ __forceinline__ uint4 ldg_cg_128(const void* p) {
    uint4 v;
    asm volatile("ld.global.cg.v4.u32 {%0,%1,%2,%3}, [%4];"
                 : "=r"(v.x), "=r"(v.y), "=r"(v.z), "=r"(v.w) : "l"(p));
    return v;
}
__device__ __forceinline__ uint32_t h2_bits(__half2 h) {
    uint32_t u;
    memcpy(&u, &h, 4);
    return u;
}

constexpr int SMEM_BYTES = 40 * 4096;   // 160 KB: B slice [kc40][wn4][gp2][lane32][16B]

// ---- persistent kernel: grid (16 hb, 8 mb), 512 threads = 16 warps (4 wm x 4 wn)
__global__ __launch_bounds__(512, 1) void lstm_persist_kernel(const float* __restrict__ bias)
{
    extern __shared__ char sB[];
    const int hb  = blockIdx.x;
    const int mb  = blockIdx.y;
    const int tid = threadIdx.x;
    const int wid = tid >> 5;
    const int lane = tid & 31;
    const int wn = wid & 3;
    const int wm = wid >> 2;      // 0..3 -> mtiles {2wm, 2wm+1}
    const int qid = lane >> 2;
    const int qtr = lane & 3;

    // load persistent B slice into smem (once)
    {
        const uint4* src = reinterpret_cast<const uint4*>(g_wp) + (size_t)hb * (SMEM_BYTES / 16);
        uint4* dst = reinterpret_cast<uint4*>(sB);
        for (int i = tid; i < SMEM_BYTES / 16; i += 512) dst[i] = src[i];
    }
    float bs[4][2];
#pragma unroll
    for (int g = 0; g < 4; g++)
#pragma unroll
        for (int u = 0; u < 2; u++)
            bs[g][u] = bias[g * HID + hb * 32 + wn * 8 + qtr * 2 + u];

    float creg[2][2][2];
#pragma unroll
    for (int mt = 0; mt < 2; mt++)
#pragma unroll
        for (int h = 0; h < 2; h++)
#pragma unroll
            for (int u = 0; u < 2; u++)
                creg[mt][h][u] = 0.0f;

    float acc[2][4][4];

    // x-part MMA for step tt (acc must be pre-zeroed)
    auto x_mma = [&](int tt) {
        const uint4* ax = reinterpret_cast<const uint4*>(
            g_xp + ((size_t)(mb * 256 + tt) * 8) * 2048);
#pragma unroll
        for (int kc = 0; kc < 8; kc++) {
            uint4 a0 = ax[(size_t)kc * 256 + (wm * 2 + 0) * 32 + lane];
            uint4 a1 = ax[(size_t)kc * 256 + (wm * 2 + 1) * 32 + lane];
            const uint4* bp = reinterpret_cast<const uint4*>(
                sB + kc * 4096 + (wn * 2) * 512 + lane * 16);
            uint4 b0 = bp[0];
            uint4 b1 = bp[32];
            mma_f16(acc[0][0], a0, b0.x, b0.y);
            mma_f16(acc[0][1], a0, b0.z, b0.w);
            mma_f16(acc[0][2], a0, b1.x, b1.y);
            mma_f16(acc[0][3], a0, b1.z, b1.w);
            mma_f16(acc[1][0], a1, b0.x, b0.y);
            mma_f16(acc[1][1], a1, b0.z, b0.w);
            mma_f16(acc[1][2], a1, b1.x, b1.y);
            mma_f16(acc[1][3], a1, b1.z, b1.w);
        }
    };
    auto zero_acc = [&]() {
#pragma unroll
        for (int mt = 0; mt < 2; mt++)
#pragma unroll
            for (int g = 0; g < 4; g++)
#pragma unroll
                for (int q = 0; q < 4; q++)
                    acc[mt][g][q] = 0.0f;
    };

    __syncthreads();
    unsigned gen = g_bgen[mb * 32];

    const int kc_h  = hb * 2 + (wn >> 1);
    const int khalf = wn & 1;

    // prologue: x part of t=0 (h0 = 0 so no h part)
    zero_acc();
    x_mma(0);

    for (int t = 0; t < SEQT; t++) {
        // ---- h chunks (kc 8..39): L2 loads; h(t) was released by previous barrier
        if (t > 0) {
            const __half* ah = g_hp + ((size_t)((t & 1) * 8 + mb) * 32) * 2048;
#pragma unroll 8
            for (int kc = 0; kc < 32; kc++) {
                uint4 a0 = ldg_cg_128(ah + ((size_t)kc * 8 + wm * 2 + 0) * 256 + lane * 8);
                uint4 a1 = ldg_cg_128(ah + ((size_t)kc * 8 + wm * 2 + 1) * 256 + lane * 8);
                const uint4* bp = reinterpret_cast<const uint4*>(
                    sB + (kc + 8) * 4096 + (wn * 2) * 512 + lane * 16);
                uint4 b0 = bp[0];
                uint4 b1 = bp[32];
                mma_f16(acc[0][0], a0, b0.x, b0.y);
                mma_f16(acc[0][1], a0, b0.z, b0.w);
                mma_f16(acc[0][2], a0, b1.x, b1.y);
                mma_f16(acc[0][3], a0, b1.z, b1.w);
                mma_f16(acc[1][0], a1, b0.x, b0.y);
                mma_f16(acc[1][1], a1, b0.z, b0.w);
                mma_f16(acc[1][2], a1, b1.x, b1.y);
                mma_f16(acc[1][3], a1, b1.z, b1.w);
            }
        }

        // ---- LSTM epilogue: c in regs, h(t+1) written as packed fragments
        const int hbuf = (t + 1) & 1;
#pragma unroll
        for (int mt = 0; mt < 2; mt++) {
            float res[2][2];
#pragma unroll
            for (int half = 0; half < 2; half++) {
#pragma unroll
                for (int u = 0; u < 2; u++) {
                    int q = half * 2 + u;
                    float gi = acc[mt][0][q] + bs[0][u];
                    float gf = acc[mt][1][q] + bs[1][u];
                    float gg = acc[mt][2][q] + bs[2][u];
                    float go = acc[mt][3][q] + bs[3][u];
                    float iv = sigmoidf_(gi);
                    float fv = sigmoidf_(gf);
                    float gv = softplusf_(gg);
                    float ov = sigmoidf_(go);
                    float cn = fv * creg[mt][half][u] + iv * gv;
                    creg[mt][half][u] = cn;
                    res[half][u] = ov * softplusf_(cn);
                }
            }
            __half2 r0 = __floats2half2_rn(res[0][0], res[0][1]);
            __half2 r1 = __floats2half2_rn(res[1][0], res[1][1]);
            size_t off = (((size_t)(hbuf * 8 + mb) * 32 + kc_h) * 8 + (wm * 2 + mt)) * 256
                         + (size_t)(qid * 4 + qtr) * 8 + khalf * 4;
            uint2 val;
            val.x = h2_bits(r0);
            val.y = h2_bits(r1);
            *reinterpret_cast<uint2*>(g_hp + off) = val;
        }

        // ---- barrier with x-compute overlap (skip after last step)
        if (t + 1 < SEQT) {
            __threadfence();
            __syncthreads();
            if (tid == 0) {
                unsigned ticket = atomicAdd(&g_bcnt[mb * 32], 1u);
                if (ticket == 15u) {
                    atomicExch(&g_bcnt[mb * 32], 0u);
                    __threadfence();
                    g_bgen[mb * 32] = gen + 1u;   // release immediately
                }
            }
            // overlap: x part of step t+1 (independent of other CTAs)
            zero_acc();
            x_mma(t + 1);
            if (tid == 0) {
                while (g_bgen[mb * 32] == gen) __nanosleep(16);
            }
            __syncthreads();
            gen = gen + 1u;
            __threadfence();
        }
    }
}

// ---- pack weights into fp16 fragment order
__global__ void pack_w_kernel(const float* __restrict__ W, const float* __restrict__ U) {
    int idx = blockIdx.x * blockDim.x + threadIdx.x;
    if (idx >= 16 * 40 * 4 * 2 * 32) return;
    int lane = idx & 31;
    int gp   = (idx >> 5) & 1;
    int wn   = (idx >> 6) & 3;
    int rest = idx >> 8;
    int kc = rest % 40;
    int hb = rest / 40;
    int qid = lane >> 2, qtr = lane & 3;
    __half2 h2[4];
#pragma unroll
    for (int g2 = 0; g2 < 2; g2++) {
        int col = (gp * 2 + g2) * HID + hb * 32 + wn * 8 + qid;
#pragma unroll
        for (int hi = 0; hi < 2; hi++) {
            int k = kc * 16 + qtr * 2 + hi * 8;
            float v0 = (k     < DIN) ? W[(size_t)k * G4 + col]       : U[(size_t)(k - DIN) * G4 + col];
            float v1 = (k + 1 < DIN) ? W[(size_t)(k + 1) * G4 + col] : U[(size_t)(k + 1 - DIN) * G4 + col];
            h2[g2 * 2 + hi] = __floats2half2_rn(v0, v1);
        }
    }
    __half* dst = g_wp + ((((size_t)(hb * 40 + kc) * 4 + wn) * 2 + gp) * 32 + lane) * 8;
    *reinterpret_cast<uint4*>(dst) = *reinterpret_cast<uint4*>(h2);
}

// ---- pack x via smem staging: block per (t, mb); coalesced reads, fragment writes
__global__ __launch_bounds__(256) void pack_x_kernel(const float* __restrict__ x) {
    __shared__ __half s[128 * 136];     // [row][d], pad 136 halves/row
    const int t  = blockIdx.x;
    const int mb = blockIdx.y;
    const int tid = threadIdx.x;
    // load: 128 rows x 32 float4 (coalesced 512B per row)
    for (int i = tid; i < 128 * 32; i += 256) {
        int row = i >> 5, q4 = i & 31;
        const float4 v = *reinterpret_cast<const float4*>(
            x + ((size_t)(mb * 128 + row) * SEQT + t) * DIN + q4 * 4);
        __half2 lo = __floats2half2_rn(v.x, v.y);
        __half2 hi = __floats2half2_rn(v.z, v.w);
        __half* p = s + row * 136 + q4 * 4;
        *reinterpret_cast<__half2*>(p)     = lo;
        *reinterpret_cast<__half2*>(p + 2) = hi;
    }
    __syncthreads();
    // write fragments: 2048 uint4 outputs (kc8 x mtile8 x lane32)
    for (int o = tid; o < 2048; o += 256) {
        int lane = o & 31, mtile = (o >> 5) & 7, kc = o >> 8;
        int qid = lane >> 2, qtr = lane & 3;
        int row0 = mtile * 16 + qid;
        int k0 = kc * 16 + qtr * 2;
        __half2 h2[4];
        h2[0] = *reinterpret_cast<const __half2*>(s + row0 * 136 + k0);
        h2[1] = *reinterpret_cast<const __half2*>(s + (row0 + 8) * 136 + k0);
        h2[2] = *reinterpret_cast<const __half2*>(s + row0 * 136 + k0 + 8);
        h2[3] = *reinterpret_cast<const __half2*>(s + (row0 + 8) * 136 + k0 + 8);
        __half* dst = g_xp + ((((size_t)(mb * 256 + t) * 8 + kc) * 8 + mtile) * 32 + lane) * 8;
        *reinterpret_cast<uint4*>(dst) = *reinterpret_cast<uint4*>(h2);
    }
}

// ---- head: 64 blocks x 256 threads, 16 rows/block, weight reuse across 4 rows/thread
__global__ __launch_bounds__(256) void vae_head_kernel(
    const float* __restrict__ eps,
    const float* __restrict__ Wm, const float* __restrict__ bm,
    const float* __restrict__ Wv, const float* __restrict__ bv,
    float* __restrict__ out)
{
    __shared__ float hs[16][514];
    const int blk = blockIdx.x;
    const int tid = threadIdx.x;
    for (int i = tid; i < 16 * HID; i += 256) {
        int row = i >> 9, k = i & 511;
        int b = blk * 16 + row;
        int mb = b >> 7, r = b & 127;
        int mtile = r >> 4, qid = r & 7, half = (r >> 3) & 1;
        int kc = k >> 4, kin = k & 15;
        int kh = kin >> 3, qtr = (kin >> 1) & 3, u = kin & 1;
        size_t off = (((size_t)mb * 32 + kc) * 8 + mtile) * 256
                     + (size_t)(qid * 4 + qtr) * 8 + (half + 2 * kh) * 2 + u;
        hs[row][k] = __half2float(g_hp[off]);
    }
    __syncthreads();
    const int z = tid & 63, rsub = tid >> 6;
    float am[4] = {0, 0, 0, 0}, av[4] = {0, 0, 0, 0};
#pragma unroll 4
    for (int k = 0; k < HID; k++) {
        float wm = Wm[(size_t)k * ZD + z];
        float wv = Wv[(size_t)k * ZD + z];
#pragma unroll
        for (int r = 0; r < 4; r++) {
            float hv = hs[rsub * 4 + r][k];
            am[r] = fmaf(hv, wm, am[r]);
            av[r] = fmaf(hv, wv, av[r]);
        }
    }
#pragma unroll
    for (int r = 0; r < 4; r++) {
        int b = blk * 16 + rsub * 4 + r;
        float mu = am[r] + bm[z];
        float lv = av[r] + bv[z];
        size_t o = (size_t)b * ZD + z;
        out[o]                          = mu;
        out[(size_t)BATCH * ZD + o]     = lv;
        out[2 * (size_t)BATCH * ZD + o] = mu + eps[o] * __expf(0.5f * lv);
    }
}

extern "C" void kernel_launch(void* const* d_in, const int* in_sizes, int n_in,
                              void* d_out, int out_size)
{
    const float* x    = (const float*)d_in[0];
    const float* eps  = (const float*)d_in[1];
    const float* W    = (const float*)d_in[2];
    const float* U    = (const float*)d_in[3];
    const float* bias = (const float*)d_in[4];
    const float* Wm   = (const float*)d_in[5];
    const float* bm   = (const float*)d_in[6];
    const float* Wv   = (const float*)d_in[7];
    const float* bv   = (const float*)d_in[8];
    float* out = (float*)d_out;

    cudaFuncSetAttribute(lstm_persist_kernel,
                         cudaFuncAttributeMaxDynamicSharedMemorySize, SMEM_BYTES);

    pack_w_kernel<<<640, 256>>>(W, U);
    pack_x_kernel<<<dim3(256, 8), 256>>>(x);

    lstm_persist_kernel<<<dim3(16, 8), 512, SMEM_BYTES>>>(bias);

    vae_head_kernel<<<64, 256>>>(eps, Wm, bm, Wv, bv, out);
}